// round 4
// baseline (speedup 1.0000x reference)
#include <cuda_runtime.h>

#define NT     256         // threads per CTA
#define VPT    8           // float4 vectors per thread (8*4*256 = 8192)
#define COLS   8192        // row length
#define CAP    1024        // SMEM candidate buffer capacity
#define NSAMP  2048        // samples per row (every 4th element)

// Monotone mapping: float -> uint32 such that float order == unsigned order.
__device__ __forceinline__ unsigned mono(float f) {
    unsigned u = __float_as_uint(f);
    return (u & 0x80000000u) ? ~u : (u | 0x80000000u);
}

// Inverse of mono(). Clamps NaN bit patterns (from synthetic bin edges) to +-inf.
__device__ __forceinline__ float inv_mono(unsigned k) {
    unsigned u = (k & 0x80000000u) ? (k & 0x7FFFFFFFu) : ~k;
    if ((u & 0x7F800000u) == 0x7F800000u && (u & 0x007FFFFFu))
        u = (u & 0x80000000u) | 0x7F800000u;
    return __uint_as_float(u);
}

// Warp-0 collective: walk a 1024-bin histogram from the TOP bin down, find the
// bin where the cumulative count first reaches rr. Returns that bin and the
// residual rank inside it. All 32 lanes of warp 0 must call this.
__device__ __forceinline__ void rank_walk(const unsigned* hist, unsigned rr, int lane,
                                          unsigned& bin_out, unsigned& nr_out) {
    const int base = 1024 - 32 * (lane + 1);   // lane 0 owns the TOP 32 bins
    unsigned s = 0;
#pragma unroll
    for (int i = 0; i < 32; i++) s += hist[base + i];
    unsigned p = s, t;
    t = __shfl_up_sync(0xFFFFFFFFu, p, 1);  if (lane >= 1)  p += t;
    t = __shfl_up_sync(0xFFFFFFFFu, p, 2);  if (lane >= 2)  p += t;
    t = __shfl_up_sync(0xFFFFFFFFu, p, 4);  if (lane >= 4)  p += t;
    t = __shfl_up_sync(0xFFFFFFFFu, p, 8);  if (lane >= 8)  p += t;
    t = __shfl_up_sync(0xFFFFFFFFu, p, 16); if (lane >= 16) p += t;
    const unsigned excl = p - s;
    const bool hit = (excl < rr) && (rr <= p);
    const unsigned m = __ballot_sync(0xFFFFFFFFu, hit);
    unsigned bin = 0, nr = rr;
    if (m) {
        const int hl = __ffs(m) - 1;
        if (lane == hl) {
            unsigned cum = excl;
            for (int b = base + 31; b >= base; b--) {
                cum += hist[b];
                if (cum >= rr) { bin = (unsigned)b; nr = rr - (cum - hist[b]); break; }
            }
        }
        bin = __shfl_sync(0xFFFFFFFFu, bin, hl);
        nr  = __shfl_sync(0xFFFFFFFFu, nr, hl);
    }
    bin_out = bin; nr_out = nr;
}

__global__ void __launch_bounds__(NT, 6) ksparse_kernel(const float* __restrict__ in,
                                                        const int* __restrict__ kp,
                                                        float* __restrict__ out) {
    __shared__ unsigned buf[CAP];      // 4 KB: bracket candidates (mono keys)
    __shared__ unsigned hist[1024];    // 4 KB
    __shared__ int s_nbuf, s_cnt;
    __shared__ unsigned s_bin, s_bin2, s_rank;
    __shared__ float s_T;

    const int tid  = threadIdx.x;
    const int lane = tid & 31;
    const int wid  = tid >> 5;

    const float4* rp = (const float4*)(in  + (size_t)blockIdx.x * COLS);
    float4*       op = (float4*)      (out + (size_t)blockIdx.x * COLS);

    const int K = kp ? __ldg(kp) : 512;
    const unsigned r = (unsigned)(K + 1);   // rank of threshold (descending, 1-indexed)

    hist[tid] = 0; hist[tid + NT] = 0; hist[tid + 2 * NT] = 0; hist[tid + 3 * NT] = 0;
    if (tid == 0) { s_nbuf = 0; s_cnt = 0; }
    __syncthreads();

    // ---- Phase 1: full-row read (warms L1/L2) + sample every 4th element ----
#pragma unroll
    for (int i = 0; i < VPT; i++) {
        const float4 x4 = rp[tid + i * NT];
        atomicAdd(&hist[mono(x4.x) >> 22], 1u);
    }
    __syncthreads();

    // ---- Phase 2: bracket pivot selection (warp 0) ----
    if (wid == 0) {
        const float ex = (float)r * ((float)NSAMP / (float)COLS);  // expected sample rank
        const float sd = sqrtf(ex + 4.0f);
        int hi_cut = (int)(ex - 5.0f * sd - 2.0f); if (hi_cut < 0)     hi_cut = 0;
        int lo_cut = (int)(ex + 5.0f * sd + 8.0f); if (lo_cut > NSAMP) lo_cut = NSAMP;
        unsigned b, b2, nr;
        rank_walk(hist, (unsigned)hi_cut + 1u, lane, b, nr);
        rank_walk(hist, (unsigned)lo_cut,      lane, b2, nr);
        if (lane == 0) { s_bin = b; s_bin2 = b2; }
    }
    __syncthreads();
    const unsigned HI_bin = s_bin, LO_bin = s_bin2;
    const float U_hi = inv_mono(((HI_bin + 1u) << 22) - 1u);  // upper edge of HI_bin
    const float U_lo = (LO_bin == 0u) ? __int_as_float(0xFF800000)
                                      : inv_mono((LO_bin << 22) - 1u);

    // ---- Phase 3: exact count above bracket + warp-aggregated candidate push ----
    int chi = 0;
#pragma unroll
    for (int i = 0; i < VPT; i++) {
        const float4 x4 = rp[tid + i * NT];     // L1/L2 hit
#pragma unroll
        for (int j = 0; j < 4; j++) {
            const float x = (&x4.x)[j];
            const bool a = x > U_hi;
            const bool c = (x > U_lo) && !a;
            chi += a ? 1 : 0;
            const unsigned bm = __ballot_sync(0xFFFFFFFFu, c);
            if (bm) {
                const int leader = __ffs(bm) - 1;
                int base;
                if (lane == leader) base = atomicAdd(&s_nbuf, __popc(bm));
                base = __shfl_sync(0xFFFFFFFFu, base, leader);
                if (c) {
                    const int pos = base + __popc(bm & ((1u << lane) - 1u));
                    if (pos < CAP) buf[pos] = mono(x);
                }
            }
        }
    }
#pragma unroll
    for (int off = 16; off; off >>= 1) chi += __shfl_down_sync(0xFFFFFFFFu, chi, off);
    if (lane == 0) atomicAdd(&s_cnt, chi);
    __syncthreads();

    const int CHI  = s_cnt;
    const int nbuf = s_nbuf;
    const int rr0  = (int)r - CHI;
    const bool ok  = (nbuf <= CAP) && (rr0 >= 1) && (rr0 <= nbuf);

    if (ok) {
        // ---- Phase 4: exact rank-select in SMEM buffer (10+10+10+2 bit radix) ----
        unsigned pfx = 0;
        unsigned rank = (unsigned)rr0;
        for (int lvl = 0; lvl < 4; lvl++) {
            __syncthreads();
            hist[tid] = 0; hist[tid + NT] = 0; hist[tid + 2 * NT] = 0; hist[tid + 3 * NT] = 0;
            __syncthreads();
            const int plen = lvl * 10;
            for (int i = tid; i < nbuf; i += NT) {
                const unsigned key = buf[i];
                const bool match = (((key ^ pfx) >> (31 - plen)) >> 1) == 0u;
                if (match) {
                    const unsigned d = (lvl < 3) ? ((key >> (22 - plen)) & 1023u)
                                                 : (key & 3u);
                    atomicAdd(&hist[d], 1u);
                }
            }
            __syncthreads();
            if (wid == 0) {
                unsigned b, nr;
                rank_walk(hist, rank, lane, b, nr);
                if (lane == 0) { s_bin = b; s_rank = nr; }
            }
            __syncthreads();
            const unsigned d = s_bin;
            rank = s_rank;
            pfx |= (lvl < 3) ? (d << (22 - plen)) : d;
        }
        if (tid == 0) s_T = inv_mono(pfx);
    } else {
        // ---- Fallback: exact 32-bit bisection over global (L2-resident) row ----
        unsigned pfx = 0;
        for (int bit = 31; bit >= 0; bit--) {
            const unsigned cand = pfx | (1u << bit);
            int c = 0;
            for (int i = 0; i < VPT; i++) {
                const float4 x4 = rp[tid + i * NT];
                c += (mono(x4.x) >= cand) + (mono(x4.y) >= cand)
                   + (mono(x4.z) >= cand) + (mono(x4.w) >= cand);
            }
#pragma unroll
            for (int off = 16; off; off >>= 1) c += __shfl_down_sync(0xFFFFFFFFu, c, off);
            __syncthreads();
            if (tid == 0) s_cnt = 0;
            __syncthreads();
            if (lane == 0) atomicAdd(&s_cnt, c);
            __syncthreads();
            if ((unsigned)s_cnt >= r) pfx = cand;
        }
        if (tid == 0) s_T = inv_mono(pfx);
    }
    __syncthreads();
    const float T = s_T;

    // ---- Phase 5: re-read from cache, mask, single global write ----
#pragma unroll
    for (int i = 0; i < VPT; i++) {
        const float4 x4 = rp[tid + i * NT];     // L1/L2 hit
        float4 o;
        o.x = x4.x > T ? x4.x : 0.0f;
        o.y = x4.y > T ? x4.y : 0.0f;
        o.z = x4.z > T ? x4.z : 0.0f;
        o.w = x4.w > T ? x4.w : 0.0f;
        op[tid + i * NT] = o;
    }
}

extern "C" void kernel_launch(void* const* d_in, const int* in_sizes, int n_in,
                              void* d_out, int out_size) {
    const float* in = (const float*)d_in[0];
    const int*   kp = (n_in >= 2) ? (const int*)d_in[1] : nullptr;
    float* out = (float*)d_out;
    const int rows = in_sizes[0] / COLS;
    ksparse_kernel<<<rows, NT>>>(in, kp, out);
}

// round 5
// speedup vs baseline: 2.1705x; 2.1705x over previous
#include <cuda_runtime.h>

#define NT   256          // threads per CTA
#define VPT  8            // float4 vectors per thread (8*4*256 = 8192)
#define COLS 8192         // row length
#define CAP  2048         // SMEM candidate buffer capacity

// Monotone mapping: float -> uint32 such that float order == unsigned order.
__device__ __forceinline__ unsigned mono(float f) {
    unsigned u = __float_as_uint(f);
    return (u & 0x80000000u) ? ~u : (u | 0x80000000u);
}

// Inverse of mono(). Clamps NaN bit patterns (from synthetic bin edges) to +-inf.
__device__ __forceinline__ float inv_mono(unsigned k) {
    unsigned u = (k & 0x80000000u) ? (k & 0x7FFFFFFFu) : ~k;
    if ((u & 0x7F800000u) == 0x7F800000u && (u & 0x007FFFFFu))
        u = (u & 0x80000000u) | 0x7F800000u;
    return __uint_as_float(u);
}

// Warp-0 collective: walk a 1024-bin histogram from the TOP bin down, find the
// bin where the cumulative count first reaches rr. Returns that bin and the
// residual rank inside it. All 32 lanes of warp 0 must call this.
__device__ __forceinline__ void rank_walk(const unsigned* hist, unsigned rr, int lane,
                                          unsigned& bin_out, unsigned& nr_out) {
    const int base = 1024 - 32 * (lane + 1);   // lane 0 owns the TOP 32 bins
    unsigned s = 0;
#pragma unroll
    for (int i = 0; i < 32; i++) s += hist[base + i];
    unsigned p = s, t;
    t = __shfl_up_sync(0xFFFFFFFFu, p, 1);  if (lane >= 1)  p += t;
    t = __shfl_up_sync(0xFFFFFFFFu, p, 2);  if (lane >= 2)  p += t;
    t = __shfl_up_sync(0xFFFFFFFFu, p, 4);  if (lane >= 4)  p += t;
    t = __shfl_up_sync(0xFFFFFFFFu, p, 8);  if (lane >= 8)  p += t;
    t = __shfl_up_sync(0xFFFFFFFFu, p, 16); if (lane >= 16) p += t;
    const unsigned excl = p - s;
    const bool hit = (excl < rr) && (rr <= p);
    const unsigned m = __ballot_sync(0xFFFFFFFFu, hit);
    unsigned bin = 0, nr = rr;
    if (m) {
        const int hl = __ffs(m) - 1;
        if (lane == hl) {
            unsigned cum = excl;
            for (int b = base + 31; b >= base; b--) {
                cum += hist[b];
                if (cum >= rr) { bin = (unsigned)b; nr = rr - (cum - hist[b]); break; }
            }
        }
        bin = __shfl_sync(0xFFFFFFFFu, bin, hl);
        nr  = __shfl_sync(0xFFFFFFFFu, nr, hl);
    }
    bin_out = bin; nr_out = nr;
}

__global__ void __launch_bounds__(NT, 4) ksparse_kernel(const float* __restrict__ in,
                                                        const int* __restrict__ kp,
                                                        float* __restrict__ out) {
    __shared__ unsigned buf[CAP];      // 8 KB: bracket candidates (mono keys)
    __shared__ unsigned hist[1024];    // 4 KB
    __shared__ unsigned warpsum[8];
    __shared__ int s_cnt;
    __shared__ unsigned s_bin, s_bin2, s_rank;
    __shared__ float s_T;

    const int tid  = threadIdx.x;
    const int lane = tid & 31;
    const int wid  = tid >> 5;

    const float4* rp = (const float4*)(in  + (size_t)blockIdx.x * COLS);
    float4*       op = (float4*)      (out + (size_t)blockIdx.x * COLS);

    // Entire row resident in registers: one global read.
    float4 v[VPT];
#pragma unroll
    for (int i = 0; i < VPT; i++) v[i] = rp[tid + i * NT];

    const int K = kp ? __ldg(kp) : 512;
    const unsigned r = (unsigned)(K + 1);   // rank of threshold (descending, 1-indexed)

    hist[tid] = 0; hist[tid + NT] = 0; hist[tid + 2 * NT] = 0; hist[tid + 3 * NT] = 0;
    __syncthreads();

    // ---- Phase 1: sample histogram (2 samples/thread = 512) ----
    atomicAdd(&hist[mono(v[0].x) >> 22], 1u);
    atomicAdd(&hist[mono(v[4].x) >> 22], 1u);
    __syncthreads();

    // ---- Phase 2: bracket pivot selection (warp 0) ----
    if (wid == 0) {
        const float ex = (float)r * (512.0f / (float)COLS);   // expected sample rank
        const float sd = sqrtf(ex + 4.0f);
        int hi_cut = (int)(ex - 5.0f * sd - 2.0f); if (hi_cut < 0)   hi_cut = 0;
        int lo_cut = (int)(ex + 5.0f * sd + 8.0f); if (lo_cut > 512) lo_cut = 512;
        unsigned b, b2, nr;
        rank_walk(hist, (unsigned)hi_cut + 1u, lane, b, nr);
        rank_walk(hist, (unsigned)lo_cut,      lane, b2, nr);
        if (lane == 0) { s_bin = b; s_bin2 = b2; }
    }
    __syncthreads();
    const unsigned HI_bin = s_bin, LO_bin = s_bin2;
    const float U_hi = inv_mono(((HI_bin + 1u) << 22) - 1u);  // upper edge of HI_bin
    const float U_lo = (LO_bin == 0u) ? __int_as_float(0xFF800000)
                                      : inv_mono((LO_bin << 22) - 1u);

    // ---- Phase 3a: predicate masks over registers (no atomics, no branches) ----
    unsigned mhi = 0, mbr = 0;
#pragma unroll
    for (int i = 0; i < VPT; i++) {
#pragma unroll
        for (int j = 0; j < 4; j++) {
            const float x = (&v[i].x)[j];
            const bool a = x > U_hi;
            const bool b = (x > U_lo) && !a;
            mhi |= ((unsigned)a) << (i * 4 + j);
            mbr |= ((unsigned)b) << (i * 4 + j);
        }
    }
    // Packed block scan: high 16 bits = count(>U_hi), low 16 = bracket count.
    const unsigned packed = (__popc(mhi) << 16) | (unsigned)__popc(mbr);
    unsigned inc = packed, t;
    t = __shfl_up_sync(0xFFFFFFFFu, inc, 1);  if (lane >= 1)  inc += t;
    t = __shfl_up_sync(0xFFFFFFFFu, inc, 2);  if (lane >= 2)  inc += t;
    t = __shfl_up_sync(0xFFFFFFFFu, inc, 4);  if (lane >= 4)  inc += t;
    t = __shfl_up_sync(0xFFFFFFFFu, inc, 8);  if (lane >= 8)  inc += t;
    t = __shfl_up_sync(0xFFFFFFFFu, inc, 16); if (lane >= 16) inc += t;
    if (lane == 31) warpsum[wid] = inc;
    __syncthreads();
    if (wid == 0) {
        unsigned w = (lane < 8) ? warpsum[lane] : 0;
        t = __shfl_up_sync(0xFFFFFFFFu, w, 1); if (lane >= 1) w += t;
        t = __shfl_up_sync(0xFFFFFFFFu, w, 2); if (lane >= 2) w += t;
        t = __shfl_up_sync(0xFFFFFFFFu, w, 4); if (lane >= 4) w += t;
        if (lane < 8) warpsum[lane] = w;
    }
    __syncthreads();
    const unsigned tot  = warpsum[7];
    const unsigned excl = (wid ? warpsum[wid - 1] : 0u) + inc - packed;
    const int CHI  = (int)(tot >> 16);
    const int nbuf = (int)(tot & 0xFFFFu);
    int pos = (int)(excl & 0xFFFFu);

    // ---- Phase 3b: push bracket candidates to owned slots ----
#pragma unroll
    for (int i = 0; i < VPT; i++) {
#pragma unroll
        for (int j = 0; j < 4; j++) {
            if ((mbr >> (i * 4 + j)) & 1u) {
                if (pos < CAP) buf[pos] = mono((&v[i].x)[j]);
                pos++;
            }
        }
    }
    __syncthreads();

    const int rr0 = (int)r - CHI;
    const bool ok = (nbuf <= CAP) && (rr0 >= 1) && (rr0 <= nbuf);

    if (ok) {
        // ---- Phase 4: exact rank-select in SMEM buffer (10+10+10+2 bit radix) ----
        unsigned pfx = 0;
        unsigned rank = (unsigned)rr0;
        for (int lvl = 0; lvl < 4; lvl++) {
            __syncthreads();
            hist[tid] = 0; hist[tid + NT] = 0; hist[tid + 2 * NT] = 0; hist[tid + 3 * NT] = 0;
            __syncthreads();
            const int plen = lvl * 10;
            for (int i = tid; i < nbuf; i += NT) {
                const unsigned key = buf[i];
                const bool match = (((key ^ pfx) >> (31 - plen)) >> 1) == 0u;
                if (match) {
                    const unsigned d = (lvl < 3) ? ((key >> (22 - plen)) & 1023u)
                                                 : (key & 3u);
                    atomicAdd(&hist[d], 1u);
                }
            }
            __syncthreads();
            if (wid == 0) {
                unsigned b, nr;
                rank_walk(hist, rank, lane, b, nr);
                if (lane == 0) { s_bin = b; s_rank = nr; }
            }
            __syncthreads();
            const unsigned d = s_bin;
            rank = s_rank;
            pfx |= (lvl < 3) ? (d << (22 - plen)) : d;
        }
        if (tid == 0) s_T = inv_mono(pfx);
    } else {
        // ---- Fallback: exact 32-bit bisection over register data (rare) ----
        unsigned pfx = 0;
        for (int bit = 31; bit >= 0; bit--) {
            const unsigned cand = pfx | (1u << bit);
            int c = 0;
#pragma unroll
            for (int i = 0; i < VPT; i++) {
                c += (mono(v[i].x) >= cand) + (mono(v[i].y) >= cand)
                   + (mono(v[i].z) >= cand) + (mono(v[i].w) >= cand);
            }
#pragma unroll
            for (int off = 16; off; off >>= 1) c += __shfl_down_sync(0xFFFFFFFFu, c, off);
            __syncthreads();
            if (tid == 0) s_cnt = 0;
            __syncthreads();
            if (lane == 0) atomicAdd(&s_cnt, c);
            __syncthreads();
            if ((unsigned)s_cnt >= r) pfx = cand;
        }
        if (tid == 0) s_T = inv_mono(pfx);
    }
    __syncthreads();
    const float T = s_T;

    // ---- Phase 5: mask from registers, single global write ----
#pragma unroll
    for (int i = 0; i < VPT; i++) {
        float4 o;
        o.x = v[i].x > T ? v[i].x : 0.0f;
        o.y = v[i].y > T ? v[i].y : 0.0f;
        o.z = v[i].z > T ? v[i].z : 0.0f;
        o.w = v[i].w > T ? v[i].w : 0.0f;
        op[tid + i * NT] = o;
    }
}

extern "C" void kernel_launch(void* const* d_in, const int* in_sizes, int n_in,
                              void* d_out, int out_size) {
    const float* in = (const float*)d_in[0];
    const int*   kp = (n_in >= 2) ? (const int*)d_in[1] : nullptr;
    float* out = (float*)d_out;
    const int rows = in_sizes[0] / COLS;
    ksparse_kernel<<<rows, NT>>>(in, kp, out);
}